// round 2
// baseline (speedup 1.0000x reference)
#include <cuda_runtime.h>
#include <cstdint>

// Problem constants
#define T_DIM 4096
#define B_DIM 8
#define F_DIM 512
#define H_DIM 1024

// Tile config
#define BT 64     // t rows per block
#define BH 128    // h cols per chunk
#define BF 16     // f (k) slice
#define XPAD 4    // keep 16B alignment for float4 loads from xs

__global__ __launch_bounds__(256, 3)
void mothernet_fused_kernel(const float* __restrict__ x,
                            const float* __restrict__ w1,
                            const float* __restrict__ b1,
                            const float* __restrict__ w2,
                            const float* __restrict__ b2,
                            float* __restrict__ out)
{
    __shared__ float xs[BF][BT + XPAD];   // [f][t]  (transposed x tile)
    __shared__ float ws[BF][BH];          // [f][h]
    __shared__ float red[BT];             // per-t accumulator across h-chunks

    const int tid = threadIdx.x;
    const int b   = blockIdx.y;
    const int t0  = blockIdx.x * BT;

    // compute-thread mapping: 16x16, microtile 4(t) x 8(h)
    const int ty = tid >> 4;     // 0..15 -> t rows ty*4 .. ty*4+3
    const int tx = tid & 15;     // 0..15 -> h cols tx*8 .. tx*8+7

    // x loader mapping: 64 rows x 16 f, one float4 per thread
    const int lt = tid >> 2;            // 0..63
    const int lf = (tid & 3) * 4;       // 0,4,8,12

    // w1 loader mapping: 16 f-rows x 128 h, two float4 per thread
    const int wf = tid >> 4;            // 0..15
    const int wh = (tid & 15) * 8;      // 0..120

    if (tid < BT) red[tid] = 0.0f;

    const float* xb  = x  + (size_t)t0 * B_DIM * F_DIM + (size_t)b * F_DIM;
    const float* w1b = w1 + (size_t)b * F_DIM * H_DIM;
    const float* b1b = b1 + (size_t)b * H_DIM;
    const float* w2b = w2 + (size_t)b * H_DIM;   // O = 1

    for (int hc = 0; hc < H_DIM; hc += BH) {
        float acc[4][8];
        #pragma unroll
        for (int i = 0; i < 4; i++)
            #pragma unroll
            for (int j = 0; j < 8; j++)
                acc[i][j] = 0.0f;

        // --- prologue: fetch first tile into registers ---
        float4 xv = *reinterpret_cast<const float4*>(
            xb + (size_t)lt * (B_DIM * F_DIM) + lf);
        const float* wrow0 = w1b + (size_t)wf * H_DIM + hc + wh;
        float4 w0  = *reinterpret_cast<const float4*>(wrow0);
        float4 w1v = *reinterpret_cast<const float4*>(wrow0 + 4);

        for (int fk = 0; fk < F_DIM; fk += BF) {
            __syncthreads();   // previous compute done reading smem

            // --- stage registers -> smem (with nan_to_num on x) ---
            xs[lf + 0][lt] = (xv.x == xv.x) ? xv.x : 0.0f;
            xs[lf + 1][lt] = (xv.y == xv.y) ? xv.y : 0.0f;
            xs[lf + 2][lt] = (xv.z == xv.z) ? xv.z : 0.0f;
            xs[lf + 3][lt] = (xv.w == xv.w) ? xv.w : 0.0f;
            *reinterpret_cast<float4*>(&ws[wf][wh])     = w0;
            *reinterpret_cast<float4*>(&ws[wf][wh + 4]) = w1v;

            __syncthreads();

            // --- prefetch next tile into registers (overlaps FMA body) ---
            // clamp to avoid OOB at the final slice (values unused then)
            const int fkn = (fk + BF < F_DIM) ? (fk + BF) : fk;
            xv = *reinterpret_cast<const float4*>(
                xb + (size_t)lt * (B_DIM * F_DIM) + fkn + lf);
            const float* wrow = w1b + (size_t)(fkn + wf) * H_DIM + hc + wh;
            w0  = *reinterpret_cast<const float4*>(wrow);
            w1v = *reinterpret_cast<const float4*>(wrow + 4);

            // --- FMA microkernel ---
            #pragma unroll
            for (int kk = 0; kk < BF; kk++) {
                float4 a  = *reinterpret_cast<const float4*>(&xs[kk][ty * 4]);
                float4 p0 = *reinterpret_cast<const float4*>(&ws[kk][tx * 8]);
                float4 p1 = *reinterpret_cast<const float4*>(&ws[kk][tx * 8 + 4]);
                float av[4] = {a.x, a.y, a.z, a.w};
                float bv[8] = {p0.x, p0.y, p0.z, p0.w, p1.x, p1.y, p1.z, p1.w};
                #pragma unroll
                for (int i = 0; i < 4; i++)
                    #pragma unroll
                    for (int j = 0; j < 8; j++)
                        acc[i][j] = fmaf(av[i], bv[j], acc[i][j]);
            }
        }

        // --- epilogue: +b1, relu, * w2, reduce over h ---
        const int hbase = hc + tx * 8;
        float s[4] = {0.f, 0.f, 0.f, 0.f};
        #pragma unroll
        for (int j = 0; j < 8; j++) {
            const float bb = b1b[hbase + j];
            const float ww = w2b[hbase + j];
            #pragma unroll
            for (int i = 0; i < 4; i++) {
                float hv = acc[i][j] + bb;
                hv = hv > 0.0f ? hv : 0.0f;
                s[i] = fmaf(hv, ww, s[i]);
            }
        }
        // reduce over tx (16 lanes within each half-warp)
        #pragma unroll
        for (int off = 8; off > 0; off >>= 1) {
            #pragma unroll
            for (int i = 0; i < 4; i++)
                s[i] += __shfl_down_sync(0xFFFFFFFFu, s[i], off, 16);
        }
        if (tx == 0) {
            // unique writer per t across all h-chunks: no race
            #pragma unroll
            for (int i = 0; i < 4; i++)
                red[ty * 4 + i] += s[i];
        }
    }

    __syncthreads();
    if (tid < BT) {
        out[(size_t)(t0 + tid) * B_DIM + b] = red[tid] + b2[b];
    }
}

extern "C" void kernel_launch(void* const* d_in, const int* in_sizes, int n_in,
                              void* d_out, int out_size)
{
    const float* x  = (const float*)d_in[0];   // [T,B,F]
    const float* w1 = (const float*)d_in[1];   // [B,F,H]
    const float* b1 = (const float*)d_in[2];   // [B,H]
    const float* w2 = (const float*)d_in[3];   // [B,H,O=1]
    const float* b2 = (const float*)d_in[4];   // [B,O=1]
    float* out = (float*)d_out;                // [T,B,1]

    dim3 grid(T_DIM / BT, B_DIM);
    dim3 block(256);
    mothernet_fused_kernel<<<grid, block>>>(x, w1, b1, w2, b2, out);
}

// round 4
// speedup vs baseline: 3.6414x; 3.6414x over previous
#include <cuda_runtime.h>
#include <cuda_bf16.h>
#include <cstdint>

// ---------------- problem constants ----------------
#define T_DIM 4096
#define B_DIM 8
#define F_DIM 512
#define H_DIM 1024

// ---------------- tiling ----------------
#define M_TILE 128          // t rows per CTA
#define N_CH   128          // h columns per chunk
#define NUM_CH (H_DIM / N_CH)   // 8
#define K_SL   32           // k per pipeline slice
#define NUM_SL (F_DIM / K_SL)   // 16

// smem strides (bf16 elements), padded for conflict-free ldmatrix
#define A_STRIDE 40         // 32 + 8 pad  (80 B rows)
#define B_STRIDE 136        // 128 + 8 pad (272 B rows)
#define A_BYTES (M_TILE * A_STRIDE * 2)      // 10240
#define B_BYTES (K_SL * B_STRIDE * 2)        // 8704
#define STAGE_BYTES (2 * A_BYTES + 2 * B_BYTES)  // Ah, Al, Bh, Bl = 37888
#define AH_OFF 0
#define AL_OFF A_BYTES
#define BH_OFF (2 * A_BYTES)
#define BL_OFF (2 * A_BYTES + B_BYTES)
#define SMEM_DYN (2 * STAGE_BYTES)           // 75776

// ---------------- scratch (static device arrays: allowed) ----------------
__device__ __align__(16) __nv_bfloat16 g_xhi[(size_t)T_DIM * B_DIM * F_DIM];
__device__ __align__(16) __nv_bfloat16 g_xlo[(size_t)T_DIM * B_DIM * F_DIM];
__device__ __align__(16) __nv_bfloat16 g_w1hi[(size_t)B_DIM * F_DIM * H_DIM];
__device__ __align__(16) __nv_bfloat16 g_w1lo[(size_t)B_DIM * F_DIM * H_DIM];

// ---------------- PTX helpers (base ISA only: sm_80+) ----------------
__device__ __forceinline__ uint32_t smem_u32(const void* p) {
    uint32_t a;
    asm("{ .reg .u64 t; cvta.to.shared.u64 t, %1; cvt.u32.u64 %0, t; }"
        : "=r"(a) : "l"(p));
    return a;
}
#define CP_ASYNC16(dst, src) \
    asm volatile("cp.async.cg.shared.global [%0], [%1], 16;" :: "r"(dst), "l"(src))
#define CP_COMMIT() asm volatile("cp.async.commit_group;" ::: "memory")
#define CP_WAIT0()  asm volatile("cp.async.wait_group 0;" ::: "memory")

__device__ __forceinline__ void ldsm_x4(uint32_t* r, uint32_t addr) {
    asm volatile("ldmatrix.sync.aligned.m8n8.x4.shared.b16 {%0,%1,%2,%3}, [%4];"
        : "=r"(r[0]), "=r"(r[1]), "=r"(r[2]), "=r"(r[3]) : "r"(addr));
}
__device__ __forceinline__ void ldsm_x4_t(uint32_t* r, uint32_t addr) {
    asm volatile("ldmatrix.sync.aligned.m8n8.x4.trans.shared.b16 {%0,%1,%2,%3}, [%4];"
        : "=r"(r[0]), "=r"(r[1]), "=r"(r[2]), "=r"(r[3]) : "r"(addr));
}
__device__ __forceinline__ void mma_bf16(float* d, const uint32_t* a, const uint32_t* b) {
    asm volatile(
        "mma.sync.aligned.m16n8k16.row.col.f32.bf16.bf16.f32 "
        "{%0,%1,%2,%3}, {%4,%5,%6,%7}, {%8,%9}, {%0,%1,%2,%3};"
        : "+f"(d[0]), "+f"(d[1]), "+f"(d[2]), "+f"(d[3])
        : "r"(a[0]), "r"(a[1]), "r"(a[2]), "r"(a[3]), "r"(b[0]), "r"(b[1]));
}

// ---------------- kernel 1: x -> bf16 hi/lo (with nan_to_num) ----------------
__global__ void convert_x_kernel(const float* __restrict__ x) {
    size_t i = ((size_t)blockIdx.x * blockDim.x + threadIdx.x) * 4;
    float4 v = *reinterpret_cast<const float4*>(x + i);
    float a[4] = {v.x, v.y, v.z, v.w};
    __nv_bfloat16 h[4], l[4];
#pragma unroll
    for (int j = 0; j < 4; j++) {
        if (a[j] != a[j]) a[j] = 0.0f;
        h[j] = __float2bfloat16_rn(a[j]);
        l[j] = __float2bfloat16_rn(a[j] - __bfloat162float(h[j]));
    }
    *reinterpret_cast<__nv_bfloat162*>(g_xhi + i)     = __nv_bfloat162(h[0], h[1]);
    *reinterpret_cast<__nv_bfloat162*>(g_xhi + i + 2) = __nv_bfloat162(h[2], h[3]);
    *reinterpret_cast<__nv_bfloat162*>(g_xlo + i)     = __nv_bfloat162(l[0], l[1]);
    *reinterpret_cast<__nv_bfloat162*>(g_xlo + i + 2) = __nv_bfloat162(l[2], l[3]);
}

// ---------------- kernel 2: w1 -> bf16 hi/lo (same layout [B,F,H]) ----------------
__global__ void convert_w1_kernel(const float* __restrict__ w1) {
    size_t i = ((size_t)blockIdx.x * blockDim.x + threadIdx.x) * 4;
    float4 v = *reinterpret_cast<const float4*>(w1 + i);
    float a[4] = {v.x, v.y, v.z, v.w};
    __nv_bfloat16 h[4], l[4];
#pragma unroll
    for (int j = 0; j < 4; j++) {
        h[j] = __float2bfloat16_rn(a[j]);
        l[j] = __float2bfloat16_rn(a[j] - __bfloat162float(h[j]));
    }
    *reinterpret_cast<__nv_bfloat162*>(g_w1hi + i)     = __nv_bfloat162(h[0], h[1]);
    *reinterpret_cast<__nv_bfloat162*>(g_w1hi + i + 2) = __nv_bfloat162(h[2], h[3]);
    *reinterpret_cast<__nv_bfloat162*>(g_w1lo + i)     = __nv_bfloat162(l[0], l[1]);
    *reinterpret_cast<__nv_bfloat162*>(g_w1lo + i + 2) = __nv_bfloat162(l[2], l[3]);
}

// ---------------- kernel 3: fused HMMA GEMM + epilogue ----------------
__global__ __launch_bounds__(256)
void mothernet_mma_kernel(const float* __restrict__ b1,
                          const float* __restrict__ w2,
                          const float* __restrict__ b2,
                          float* __restrict__ out)
{
    extern __shared__ char smem[];
    __shared__ float red[M_TILE];
    const uint32_t sb = smem_u32(smem);

    const int tid  = threadIdx.x;
    const int wid  = tid >> 5;
    const int lane = tid & 31;
    const int wm   = wid >> 1;          // 0..3 : rows wm*32 .. +31
    const int wn   = wid & 1;           // 0..1 : cols wn*64 .. +63
    const int b    = blockIdx.y;
    const int t0   = blockIdx.x * M_TILE;

    if (tid < M_TILE) red[tid] = 0.0f;

    const __nv_bfloat16* xhi  = g_xhi  + (size_t)t0 * (B_DIM * F_DIM) + (size_t)b * F_DIM;
    const __nv_bfloat16* xlo  = g_xlo  + (size_t)t0 * (B_DIM * F_DIM) + (size_t)b * F_DIM;
    const __nv_bfloat16* w1hi = g_w1hi + (size_t)b * F_DIM * H_DIM;
    const __nv_bfloat16* w1lo = g_w1lo + (size_t)b * F_DIM * H_DIM;
    const float* b1b = b1 + (size_t)b * H_DIM;
    const float* w2b = w2 + (size_t)b * H_DIM;

    // loader mappings
    const int ar = tid >> 1;            // A row pair: handles rows ar, each thread 2 chunks
    const int ac = (tid & 1) * 2;       // chunk 0/1 or 2/3
    const int br = tid >> 3;            // B row 0..31
    const int bc = (tid & 7) * 2;       // chunks 0..15 (2 per thread)

    __syncthreads();

    float acc[2][8][4];

    for (int ch = 0; ch < NUM_CH; ch++) {
        const int hc = ch * N_CH;
#pragma unroll
        for (int mf = 0; mf < 2; mf++)
#pragma unroll
            for (int nf = 0; nf < 8; nf++)
#pragma unroll
                for (int q = 0; q < 4; q++) acc[mf][nf][q] = 0.0f;

        // ---- prefetch slice 0 into stage 0 ----
        {
            const int fk = 0;
            const uint32_t st = sb;
#pragma unroll
            for (int u = 0; u < 2; u++) {
                const int chk = ac + u;   // 0..3
                const uint32_t ad = st + ar * 80 + chk * 16;
                const uint64_t gofs = (size_t)ar * (B_DIM * F_DIM) + fk + chk * 8;
                CP_ASYNC16(ad + AH_OFF, xhi + gofs);
                CP_ASYNC16(ad + AL_OFF, xlo + gofs);
                const int bchk = bc + u;  // 0..15
                const uint32_t bd = st + br * 272 + bchk * 16;
                const uint64_t wofs = (size_t)(fk + br) * H_DIM + hc + bchk * 8;
                CP_ASYNC16(bd + BH_OFF, w1hi + wofs);
                CP_ASYNC16(bd + BL_OFF, w1lo + wofs);
            }
            CP_COMMIT();
        }

        for (int s = 0; s < NUM_SL; s++) {
            CP_WAIT0();
            __syncthreads();

            // prefetch next slice into the other stage (overlaps compute below)
            if (s + 1 < NUM_SL) {
                const int fk = (s + 1) * K_SL;
                const uint32_t st = sb + ((s + 1) & 1) * STAGE_BYTES;
#pragma unroll
                for (int u = 0; u < 2; u++) {
                    const int chk = ac + u;
                    const uint32_t ad = st + ar * 80 + chk * 16;
                    const uint64_t gofs = (size_t)ar * (B_DIM * F_DIM) + fk + chk * 8;
                    CP_ASYNC16(ad + AH_OFF, xhi + gofs);
                    CP_ASYNC16(ad + AL_OFF, xlo + gofs);
                    const int bchk = bc + u;
                    const uint32_t bd = st + br * 272 + bchk * 16;
                    const uint64_t wofs = (size_t)(fk + br) * H_DIM + hc + bchk * 8;
                    CP_ASYNC16(bd + BH_OFF, w1hi + wofs);
                    CP_ASYNC16(bd + BL_OFF, w1lo + wofs);
                }
                CP_COMMIT();
            }

            // ---- compute on stage s&1 ----
            const uint32_t st = sb + (s & 1) * STAGE_BYTES;
#pragma unroll
            for (int ks = 0; ks < 2; ks++) {   // two k16 steps per slice
                uint32_t ah[2][4], al[2][4], bh[8][2], bl[8][2];
                // A fragments: rows wm*32 + mf*16 + lane%16, col ks*16 + (lane/16)*8
#pragma unroll
                for (int mf = 0; mf < 2; mf++) {
                    const int row = wm * 32 + mf * 16 + (lane & 15);
                    const int col = ks * 16 + (lane >> 4) * 8;
                    const uint32_t a = st + row * 80 + col * 2;
                    ldsm_x4(ah[mf], a + AH_OFF);
                    ldsm_x4(al[mf], a + AL_OFF);
                }
                // B fragments: k = ks*16 + lane%16, n = wn*64 + nq*16 + (lane/16)*8
#pragma unroll
                for (int nq = 0; nq < 4; nq++) {
                    const int krow = ks * 16 + (lane & 15);
                    const int ncol = wn * 64 + nq * 16 + (lane >> 4) * 8;
                    const uint32_t a = st + krow * 272 + ncol * 2;
                    uint32_t rh[4], rl[4];
                    ldsm_x4_t(rh, a + BH_OFF);
                    ldsm_x4_t(rl, a + BL_OFF);
                    bh[nq * 2][0] = rh[0]; bh[nq * 2][1] = rh[1];
                    bh[nq * 2 + 1][0] = rh[2]; bh[nq * 2 + 1][1] = rh[3];
                    bl[nq * 2][0] = rl[0]; bl[nq * 2][1] = rl[1];
                    bl[nq * 2 + 1][0] = rl[2]; bl[nq * 2 + 1][1] = rl[3];
                }
#pragma unroll
                for (int mf = 0; mf < 2; mf++)
#pragma unroll
                    for (int nf = 0; nf < 8; nf++) {
                        mma_bf16(acc[mf][nf], ah[mf], bh[nf]);   // hi*hi
                        mma_bf16(acc[mf][nf], ah[mf], bl[nf]);   // hi*lo
                        mma_bf16(acc[mf][nf], al[mf], bh[nf]);   // lo*hi
                    }
            }
            __syncthreads();   // all warps done reading stage s&1 before it is refilled
        }

        // ---- epilogue: +b1, relu, *w2, reduce over h ----
#pragma unroll
        for (int mf = 0; mf < 2; mf++) {
            float s0 = 0.0f, s1 = 0.0f;
#pragma unroll
            for (int nf = 0; nf < 8; nf++) {
                const int col = hc + wn * 64 + nf * 8 + (lane & 3) * 2;
                const float bb0 = __ldg(b1b + col),     bb1 = __ldg(b1b + col + 1);
                const float ww0 = __ldg(w2b + col),     ww1 = __ldg(w2b + col + 1);
                float v;
                v = fmaxf(acc[mf][nf][0] + bb0, 0.0f); s0 = fmaf(v, ww0, s0);
                v = fmaxf(acc[mf][nf][1] + bb1, 0.0f); s0 = fmaf(v, ww1, s0);
                v = fmaxf(acc[mf][nf][2] + bb0, 0.0f); s1 = fmaf(v, ww0, s1);
                v = fmaxf(acc[mf][nf][3] + bb1, 0.0f); s1 = fmaf(v, ww1, s1);
            }
            // reduce across the 4 lanes of the quad (same rows, different cols)
            s0 += __shfl_xor_sync(0xFFFFFFFFu, s0, 1);
            s0 += __shfl_xor_sync(0xFFFFFFFFu, s0, 2);
            s1 += __shfl_xor_sync(0xFFFFFFFFu, s1, 1);
            s1 += __shfl_xor_sync(0xFFFFFFFFu, s1, 2);
            if ((lane & 3) == 0) {
                const int r0 = wm * 32 + mf * 16 + (lane >> 2);
                atomicAdd(&red[r0], s0);
                atomicAdd(&red[r0 + 8], s1);
            }
        }
    }

    __syncthreads();
    if (tid < M_TILE)
        out[(size_t)(t0 + tid) * B_DIM + b] = red[tid] + __ldg(b2 + b);
}

// ---------------- launch ----------------
extern "C" void kernel_launch(void* const* d_in, const int* in_sizes, int n_in,
                              void* d_out, int out_size)
{
    const float* x  = (const float*)d_in[0];   // [T,B,F]
    const float* w1 = (const float*)d_in[1];   // [B,F,H]
    const float* b1 = (const float*)d_in[2];   // [B,H]
    const float* w2 = (const float*)d_in[3];   // [B,H,1]
    const float* b2 = (const float*)d_in[4];   // [B,1]
    float* out = (float*)d_out;                // [T,B,1]

    {
        const size_t total = (size_t)T_DIM * B_DIM * F_DIM;   // 16,777,216
        convert_x_kernel<<<(int)(total / 4 / 256), 256>>>(x);
    }
    {
        const size_t total = (size_t)B_DIM * F_DIM * H_DIM;   // 4,194,304
        convert_w1_kernel<<<(int)(total / 4 / 256), 256>>>(w1);
    }
    {
        cudaFuncSetAttribute(mothernet_mma_kernel,
                             cudaFuncAttributeMaxDynamicSharedMemorySize, SMEM_DYN);
        dim3 g(T_DIM / M_TILE, B_DIM);
        mothernet_mma_kernel<<<g, 256, SMEM_DYN>>>(b1, w2, b2, out);
    }
}

// round 6
// speedup vs baseline: 5.1315x; 1.4092x over previous
#include <cuda_runtime.h>
#include <cuda_fp16.h>
#include <cstdint>

// ---------------- problem constants ----------------
#define T_DIM 4096
#define B_DIM 8
#define F_DIM 512
#define H_DIM 1024

// ---------------- tiling ----------------
#define M_TILE 128          // t rows per CTA
#define N_CH   128          // h columns per chunk
#define NUM_CH (H_DIM / N_CH)   // 8
#define K_SL   32           // k per pipeline slice
#define NUM_SL (F_DIM / K_SL)   // 16

// smem strides (fp16 elements), padded for conflict-free ldmatrix
#define A_STRIDE 40         // 32 + 8 pad  (80 B rows)
#define B_STRIDE 136        // 128 + 8 pad (272 B rows)
#define A_BYTES (M_TILE * A_STRIDE * 2)      // 10240
#define B_BYTES (K_SL * B_STRIDE * 2)        // 8704
#define STAGE_BYTES (2 * A_BYTES + B_BYTES)  // Ah, Al, Bh = 29184
#define AH_OFF 0
#define AL_OFF A_BYTES
#define BH_OFF (2 * A_BYTES)
#define SMEM_DYN (2 * STAGE_BYTES)           // 58368

// ---------------- scratch (static device arrays: allowed) ----------------
__device__ __align__(16) __half g_xhi[(size_t)T_DIM * B_DIM * F_DIM];
__device__ __align__(16) __half g_xlo[(size_t)T_DIM * B_DIM * F_DIM];
__device__ __align__(16) __half g_w1hi[(size_t)B_DIM * F_DIM * H_DIM];

// ---------------- PTX helpers (base ISA only: sm_80+) ----------------
__device__ __forceinline__ uint32_t smem_u32(const void* p) {
    uint32_t a;
    asm("{ .reg .u64 t; cvta.to.shared.u64 t, %1; cvt.u32.u64 %0, t; }"
        : "=r"(a) : "l"(p));
    return a;
}
#define CP_ASYNC16(dst, src) \
    asm volatile("cp.async.cg.shared.global [%0], [%1], 16;" :: "r"(dst), "l"(src))
#define CP_COMMIT() asm volatile("cp.async.commit_group;" ::: "memory")
#define CP_WAIT0()  asm volatile("cp.async.wait_group 0;" ::: "memory")

__device__ __forceinline__ void ldsm_x4(uint32_t* r, uint32_t addr) {
    asm volatile("ldmatrix.sync.aligned.m8n8.x4.shared.b16 {%0,%1,%2,%3}, [%4];"
        : "=r"(r[0]), "=r"(r[1]), "=r"(r[2]), "=r"(r[3]) : "r"(addr));
}
__device__ __forceinline__ void ldsm_x4_t(uint32_t* r, uint32_t addr) {
    asm volatile("ldmatrix.sync.aligned.m8n8.x4.trans.shared.b16 {%0,%1,%2,%3}, [%4];"
        : "=r"(r[0]), "=r"(r[1]), "=r"(r[2]), "=r"(r[3]) : "r"(addr));
}
__device__ __forceinline__ void mma_f16(float* d, const uint32_t* a, const uint32_t* b) {
    asm volatile(
        "mma.sync.aligned.m16n8k16.row.col.f32.f16.f16.f32 "
        "{%0,%1,%2,%3}, {%4,%5,%6,%7}, {%8,%9}, {%0,%1,%2,%3};"
        : "+f"(d[0]), "+f"(d[1]), "+f"(d[2]), "+f"(d[3])
        : "r"(a[0]), "r"(a[1]), "r"(a[2]), "r"(a[3]), "r"(b[0]), "r"(b[1]));
}

// ---------------- kernel 1: x -> fp16 hi/lo (with nan_to_num) ----------------
__global__ void convert_x_kernel(const float* __restrict__ x) {
    size_t i = ((size_t)blockIdx.x * blockDim.x + threadIdx.x) * 4;
    float4 v = *reinterpret_cast<const float4*>(x + i);
    float a[4] = {v.x, v.y, v.z, v.w};
    __half h[4], l[4];
#pragma unroll
    for (int j = 0; j < 4; j++) {
        if (a[j] != a[j]) a[j] = 0.0f;
        h[j] = __float2half_rn(a[j]);
        l[j] = __float2half_rn(a[j] - __half2float(h[j]));
    }
    *reinterpret_cast<__half2*>(g_xhi + i)     = __half2(h[0], h[1]);
    *reinterpret_cast<__half2*>(g_xhi + i + 2) = __half2(h[2], h[3]);
    *reinterpret_cast<__half2*>(g_xlo + i)     = __half2(l[0], l[1]);
    *reinterpret_cast<__half2*>(g_xlo + i + 2) = __half2(l[2], l[3]);
}

// ---------------- kernel 2: w1 -> fp16 hi (same layout [B,F,H]) ----------------
__global__ void convert_w1_kernel(const float* __restrict__ w1) {
    size_t i = ((size_t)blockIdx.x * blockDim.x + threadIdx.x) * 4;
    float4 v = *reinterpret_cast<const float4*>(w1 + i);
    *reinterpret_cast<__half2*>(g_w1hi + i) =
        __half2(__float2half_rn(v.x), __float2half_rn(v.y));
    *reinterpret_cast<__half2*>(g_w1hi + i + 2) =
        __half2(__float2half_rn(v.z), __float2half_rn(v.w));
}

// ---------------- kernel 3: fused HMMA GEMM + epilogue ----------------
__global__ __launch_bounds__(256, 2)
void mothernet_mma_kernel(const float* __restrict__ b1,
                          const float* __restrict__ w2,
                          const float* __restrict__ b2,
                          float* __restrict__ out)
{
    extern __shared__ char smem[];
    __shared__ float red[M_TILE];
    const uint32_t sb = smem_u32(smem);

    const int tid  = threadIdx.x;
    const int wid  = tid >> 5;
    const int lane = tid & 31;
    const int wm   = wid >> 1;          // 0..3 : rows wm*32 .. +31
    const int wn   = wid & 1;           // 0..1 : cols wn*64 .. +63
    const int b    = blockIdx.y;
    const int t0   = blockIdx.x * M_TILE;

    if (tid < M_TILE) red[tid] = 0.0f;

    const __half* xhi  = g_xhi  + (size_t)t0 * (B_DIM * F_DIM) + (size_t)b * F_DIM;
    const __half* xlo  = g_xlo  + (size_t)t0 * (B_DIM * F_DIM) + (size_t)b * F_DIM;
    const __half* w1hi = g_w1hi + (size_t)b * F_DIM * H_DIM;
    const float* b1b = b1 + (size_t)b * H_DIM;
    const float* w2b = w2 + (size_t)b * H_DIM;
    const float  bias2 = __ldg(b2 + b);

    // loader mappings
    const int ar = tid >> 1;            // A row: each thread 2 chunks of 16B
    const int ac = (tid & 1) * 2;       // chunk 0/1 or 2/3
    const int br = tid >> 3;            // B row 0..31
    const int bc = (tid & 7) * 2;       // chunks 0..15 (2 per thread)

    __syncthreads();

    float acc[2][8][4];

    for (int ch = 0; ch < NUM_CH; ch++) {
        const int hc = ch * N_CH;
#pragma unroll
        for (int mf = 0; mf < 2; mf++)
#pragma unroll
            for (int nf = 0; nf < 8; nf++)
#pragma unroll
                for (int q = 0; q < 4; q++) acc[mf][nf][q] = 0.0f;

        // ---- prefetch slice 0 into stage 0 ----
        {
            const uint32_t st = sb;
#pragma unroll
            for (int u = 0; u < 2; u++) {
                const int chk = ac + u;   // 0..3
                const uint32_t ad = st + ar * 80 + chk * 16;
                const uint64_t gofs = (size_t)ar * (B_DIM * F_DIM) + chk * 8;
                CP_ASYNC16(ad + AH_OFF, xhi + gofs);
                CP_ASYNC16(ad + AL_OFF, xlo + gofs);
                const int bchk = bc + u;  // 0..15
                const uint32_t bd = st + br * 272 + bchk * 16;
                const uint64_t wofs = (size_t)br * H_DIM + hc + bchk * 8;
                CP_ASYNC16(bd + BH_OFF, w1hi + wofs);
            }
            CP_COMMIT();
        }

        for (int s = 0; s < NUM_SL; s++) {
            CP_WAIT0();
            __syncthreads();

            // prefetch next slice into the other stage (overlaps compute below)
            if (s + 1 < NUM_SL) {
                const int fk = (s + 1) * K_SL;
                const uint32_t st = sb + ((s + 1) & 1) * STAGE_BYTES;
#pragma unroll
                for (int u = 0; u < 2; u++) {
                    const int chk = ac + u;
                    const uint32_t ad = st + ar * 80 + chk * 16;
                    const uint64_t gofs = (size_t)ar * (B_DIM * F_DIM) + fk + chk * 8;
                    CP_ASYNC16(ad + AH_OFF, xhi + gofs);
                    CP_ASYNC16(ad + AL_OFF, xlo + gofs);
                    const int bchk = bc + u;
                    const uint32_t bd = st + br * 272 + bchk * 16;
                    const uint64_t wofs = (size_t)(fk + br) * H_DIM + hc + bchk * 8;
                    CP_ASYNC16(bd + BH_OFF, w1hi + wofs);
                }
                CP_COMMIT();
            }

            // ---- compute on stage s&1 ----
            const uint32_t st = sb + (s & 1) * STAGE_BYTES;
#pragma unroll
            for (int ks = 0; ks < 2; ks++) {   // two k16 steps per slice
                uint32_t ah[2][4], al[2][4], bh[8][2];
#pragma unroll
                for (int mf = 0; mf < 2; mf++) {
                    const int row = wm * 32 + mf * 16 + (lane & 15);
                    const int col = ks * 16 + (lane >> 4) * 8;
                    const uint32_t a = st + row * 80 + col * 2;
                    ldsm_x4(ah[mf], a + AH_OFF);
                    ldsm_x4(al[mf], a + AL_OFF);
                }
#pragma unroll
                for (int nq = 0; nq < 4; nq++) {
                    const int krow = ks * 16 + (lane & 15);
                    const int ncol = wn * 64 + nq * 16 + (lane >> 4) * 8;
                    uint32_t rh[4];
                    ldsm_x4_t(rh, st + krow * 272 + ncol * 2 + BH_OFF);
                    bh[nq * 2][0] = rh[0]; bh[nq * 2][1] = rh[1];
                    bh[nq * 2 + 1][0] = rh[2]; bh[nq * 2 + 1][1] = rh[3];
                }
#pragma unroll
                for (int mf = 0; mf < 2; mf++)
#pragma unroll
                    for (int nf = 0; nf < 8; nf++) {
                        mma_f16(acc[mf][nf], ah[mf], bh[nf]);   // xh * wh
                        mma_f16(acc[mf][nf], al[mf], bh[nf]);   // xl * wh
                    }
            }
            __syncthreads();   // all warps done reading stage s&1 before refill
        }

        // ---- epilogue: +b1, relu, *w2, reduce over h ----
#pragma unroll
        for (int mf = 0; mf < 2; mf++) {
            float s0 = 0.0f, s1 = 0.0f;
#pragma unroll
            for (int nf = 0; nf < 8; nf++) {
                const int col = hc + wn * 64 + nf * 8 + (lane & 3) * 2;
                const float bb0 = __ldg(b1b + col),     bb1 = __ldg(b1b + col + 1);
                const float ww0 = __ldg(w2b + col),     ww1 = __ldg(w2b + col + 1);
                float v;
                v = fmaxf(acc[mf][nf][0] + bb0, 0.0f); s0 = fmaf(v, ww0, s0);
                v = fmaxf(acc[mf][nf][1] + bb1, 0.0f); s0 = fmaf(v, ww1, s0);
                v = fmaxf(acc[mf][nf][2] + bb0, 0.0f); s1 = fmaf(v, ww0, s1);
                v = fmaxf(acc[mf][nf][3] + bb1, 0.0f); s1 = fmaf(v, ww1, s1);
            }
            s0 += __shfl_xor_sync(0xFFFFFFFFu, s0, 1);
            s0 += __shfl_xor_sync(0xFFFFFFFFu, s0, 2);
            s1 += __shfl_xor_sync(0xFFFFFFFFu, s1, 1);
            s1 += __shfl_xor_sync(0xFFFFFFFFu, s1, 2);
            if ((lane & 3) == 0) {
                const int r0 = wm * 32 + mf * 16 + (lane >> 2);
                atomicAdd(&red[r0], s0);
                atomicAdd(&red[r0 + 8], s1);
            }
        }
    }

    __syncthreads();
    if (tid < M_TILE)
        out[(size_t)(t0 + tid) * B_DIM + b] = red[tid] + bias2;
}

// ---------------- launch ----------------
extern "C" void kernel_launch(void* const* d_in, const int* in_sizes, int n_in,
                              void* d_out, int out_size)
{
    const float* x  = (const float*)d_in[0];   // [T,B,F]
    const float* w1 = (const float*)d_in[1];   // [B,F,H]
    const float* b1 = (const float*)d_in[2];   // [B,H]
    const float* w2 = (const float*)d_in[3];   // [B,H,1]
    const float* b2 = (const float*)d_in[4];   // [B,1]
    float* out = (float*)d_out;                // [T,B,1]

    {
        const size_t total = (size_t)T_DIM * B_DIM * F_DIM;   // 16,777,216
        convert_x_kernel<<<(int)(total / 4 / 256), 256>>>(x);
    }
    {
        const size_t total = (size_t)B_DIM * F_DIM * H_DIM;   // 4,194,304
        convert_w1_kernel<<<(int)(total / 4 / 256), 256>>>(w1);
    }
    {
        cudaFuncSetAttribute(mothernet_mma_kernel,
                             cudaFuncAttributeMaxDynamicSharedMemorySize, SMEM_DYN);
        dim3 g(T_DIM / M_TILE, B_DIM);
        mothernet_mma_kernel<<<g, 256, SMEM_DYN>>>(b1, w2, b2, out);
    }
}

// round 9
// speedup vs baseline: 8.2708x; 1.6118x over previous
#include <cuda_runtime.h>
#include <cuda_fp16.h>
#include <cstdint>

// ---------------- problem constants ----------------
#define T_DIM 4096
#define B_DIM 8
#define F_DIM 512
#define H_DIM 1024

// ---------------- tiling ----------------
#define M_TILE 128          // t rows per CTA
#define N_CH   128          // h columns per chunk
#define NUM_CH (H_DIM / N_CH)   // 8
#define K_SL   32           // k per pipeline slice
#define NUM_SL (F_DIM / K_SL)   // 16

// smem strides (fp16 elements), padded for conflict-free ldmatrix
#define A_STRIDE 40         // 32 + 8 pad  (80 B rows)
#define B_STRIDE 136        // 128 + 8 pad (272 B rows)
#define A_BYTES (M_TILE * A_STRIDE * 2)      // 10240
#define B_BYTES (K_SL * B_STRIDE * 2)        // 8704
#define STAGE_BYTES (A_BYTES + B_BYTES)      // Ah, Bh = 18944
#define AH_OFF 0
#define BH_OFF A_BYTES
#define SMEM_DYN (2 * STAGE_BYTES)           // 37888

// ---------------- scratch (static device arrays: allowed) ----------------
__device__ __align__(16) __half g_xhi[(size_t)T_DIM * B_DIM * F_DIM];
__device__ __align__(16) __half g_w1hi[(size_t)B_DIM * F_DIM * H_DIM];

// ---------------- PTX helpers (base ISA only: sm_80+) ----------------
__device__ __forceinline__ uint32_t smem_u32(const void* p) {
    uint32_t a;
    asm("{ .reg .u64 t; cvta.to.shared.u64 t, %1; cvt.u32.u64 %0, t; }"
        : "=r"(a) : "l"(p));
    return a;
}
#define CP_ASYNC16(dst, src) \
    asm volatile("cp.async.cg.shared.global [%0], [%1], 16;" :: "r"(dst), "l"(src))
#define CP_COMMIT() asm volatile("cp.async.commit_group;" ::: "memory")
#define CP_WAIT0()  asm volatile("cp.async.wait_group 0;" ::: "memory")

__device__ __forceinline__ void ldsm_x4(uint32_t* r, uint32_t addr) {
    asm volatile("ldmatrix.sync.aligned.m8n8.x4.shared.b16 {%0,%1,%2,%3}, [%4];"
        : "=r"(r[0]), "=r"(r[1]), "=r"(r[2]), "=r"(r[3]) : "r"(addr));
}
__device__ __forceinline__ void ldsm_x4_t(uint32_t* r, uint32_t addr) {
    asm volatile("ldmatrix.sync.aligned.m8n8.x4.trans.shared.b16 {%0,%1,%2,%3}, [%4];"
        : "=r"(r[0]), "=r"(r[1]), "=r"(r[2]), "=r"(r[3]) : "r"(addr));
}
__device__ __forceinline__ void mma_f16(float* d, const uint32_t* a, const uint32_t* b) {
    asm volatile(
        "mma.sync.aligned.m16n8k16.row.col.f32.f16.f16.f32 "
        "{%0,%1,%2,%3}, {%4,%5,%6,%7}, {%8,%9}, {%0,%1,%2,%3};"
        : "+f"(d[0]), "+f"(d[1]), "+f"(d[2]), "+f"(d[3])
        : "r"(a[0]), "r"(a[1]), "r"(a[2]), "r"(a[3]), "r"(b[0]), "r"(b[1]));
}

// ---------------- kernel 1: x -> fp16 (with nan_to_num) ----------------
__global__ void convert_x_kernel(const float* __restrict__ x) {
    size_t i = ((size_t)blockIdx.x * blockDim.x + threadIdx.x) * 4;
    float4 v = *reinterpret_cast<const float4*>(x + i);
    float a[4] = {v.x, v.y, v.z, v.w};
    __half h[4];
#pragma unroll
    for (int j = 0; j < 4; j++) {
        if (a[j] != a[j]) a[j] = 0.0f;
        h[j] = __float2half_rn(a[j]);
    }
    *reinterpret_cast<__half2*>(g_xhi + i)     = __half2(h[0], h[1]);
    *reinterpret_cast<__half2*>(g_xhi + i + 2) = __half2(h[2], h[3]);
}

// ---------------- kernel 2: w1 -> fp16 (same layout [B,F,H]) ----------------
__global__ void convert_w1_kernel(const float* __restrict__ w1) {
    size_t i = ((size_t)blockIdx.x * blockDim.x + threadIdx.x) * 4;
    float4 v = *reinterpret_cast<const float4*>(w1 + i);
    *reinterpret_cast<__half2*>(g_w1hi + i) =
        __half2(__float2half_rn(v.x), __float2half_rn(v.y));
    *reinterpret_cast<__half2*>(g_w1hi + i + 2) =
        __half2(__float2half_rn(v.z), __float2half_rn(v.w));
}

// ---------------- kernel 3: fused HMMA GEMM + epilogue ----------------
__global__ __launch_bounds__(256, 2)
void mothernet_mma_kernel(const float* __restrict__ b1,
                          const float* __restrict__ w2,
                          const float* __restrict__ b2,
                          float* __restrict__ out)
{
    extern __shared__ char smem[];
    __shared__ float red[M_TILE];
    const uint32_t sb = smem_u32(smem);

    const int tid  = threadIdx.x;
    const int wid  = tid >> 5;
    const int lane = tid & 31;
    const int wm   = wid >> 1;          // 0..3 : rows wm*32 .. +31
    const int wn   = wid & 1;           // 0..1 : cols wn*64 .. +63
    const int b    = blockIdx.y;
    const int t0   = blockIdx.x * M_TILE;

    if (tid < M_TILE) red[tid] = 0.0f;

    const __half* xhi  = g_xhi  + (size_t)t0 * (B_DIM * F_DIM) + (size_t)b * F_DIM;
    const __half* w1hi = g_w1hi + (size_t)b * F_DIM * H_DIM;
    const float* b1b = b1 + (size_t)b * H_DIM;
    const float* w2b = w2 + (size_t)b * H_DIM;
    const float  bias2 = __ldg(b2 + b);

    // loader mappings
    const int ar = tid >> 1;            // A row: each thread 2 chunks of 16B
    const int ac = (tid & 1) * 2;       // chunk 0/1 or 2/3
    const int br = tid >> 3;            // B row 0..31
    const int bc = (tid & 7) * 2;       // chunks 0..15 (2 per thread)

    __syncthreads();

    float acc[2][8][4];

    for (int ch = 0; ch < NUM_CH; ch++) {
        const int hc = ch * N_CH;
#pragma unroll
        for (int mf = 0; mf < 2; mf++)
#pragma unroll
            for (int nf = 0; nf < 8; nf++)
#pragma unroll
                for (int q = 0; q < 4; q++) acc[mf][nf][q] = 0.0f;

        // ---- prefetch slice 0 into stage 0 ----
        {
            const uint32_t st = sb;
#pragma unroll
            for (int u = 0; u < 2; u++) {
                const int chk = ac + u;   // 0..3
                const uint32_t ad = st + ar * 80 + chk * 16;
                const uint64_t gofs = (size_t)ar * (B_DIM * F_DIM) + chk * 8;
                CP_ASYNC16(ad + AH_OFF, xhi + gofs);
                const int bchk = bc + u;  // 0..15
                const uint32_t bd = st + br * 272 + bchk * 16;
                const uint64_t wofs = (size_t)br * H_DIM + hc + bchk * 8;
                CP_ASYNC16(bd + BH_OFF, w1hi + wofs);
            }
            CP_COMMIT();
        }

        for (int s = 0; s < NUM_SL; s++) {
            CP_WAIT0();
            __syncthreads();

            // prefetch next slice into the other stage (overlaps compute below)
            if (s + 1 < NUM_SL) {
                const int fk = (s + 1) * K_SL;
                const uint32_t st = sb + ((s + 1) & 1) * STAGE_BYTES;
#pragma unroll
                for (int u = 0; u < 2; u++) {
                    const int chk = ac + u;
                    const uint32_t ad = st + ar * 80 + chk * 16;
                    const uint64_t gofs = (size_t)ar * (B_DIM * F_DIM) + fk + chk * 8;
                    CP_ASYNC16(ad + AH_OFF, xhi + gofs);
                    const int bchk = bc + u;
                    const uint32_t bd = st + br * 272 + bchk * 16;
                    const uint64_t wofs = (size_t)(fk + br) * H_DIM + hc + bchk * 8;
                    CP_ASYNC16(bd + BH_OFF, w1hi + wofs);
                }
                CP_COMMIT();
            }

            // ---- compute on stage s&1 ----
            const uint32_t st = sb + (s & 1) * STAGE_BYTES;
#pragma unroll
            for (int ks = 0; ks < 2; ks++) {   // two k16 steps per slice
                uint32_t ah[2][4], bh[8][2];
#pragma unroll
                for (int mf = 0; mf < 2; mf++) {
                    const int row = wm * 32 + mf * 16 + (lane & 15);
                    const int col = ks * 16 + (lane >> 4) * 8;
                    ldsm_x4(ah[mf], st + row * 80 + col * 2 + AH_OFF);
                }
#pragma unroll
                for (int nq = 0; nq < 4; nq++) {
                    const int krow = ks * 16 + (lane & 15);
                    const int ncol = wn * 64 + nq * 16 + (lane >> 4) * 8;
                    uint32_t rh[4];
                    ldsm_x4_t(rh, st + krow * 272 + ncol * 2 + BH_OFF);
                    bh[nq * 2][0] = rh[0]; bh[nq * 2][1] = rh[1];
                    bh[nq * 2 + 1][0] = rh[2]; bh[nq * 2 + 1][1] = rh[3];
                }
#pragma unroll
                for (int mf = 0; mf < 2; mf++)
#pragma unroll
                    for (int nf = 0; nf < 8; nf++)
                        mma_f16(acc[mf][nf], ah[mf], bh[nf]);
            }
            __syncthreads();   // all warps done reading stage s&1 before refill
        }

        // ---- epilogue: +b1, relu, *w2, reduce over h ----
#pragma unroll
        for (int mf = 0; mf < 2; mf++) {
            float s0 = 0.0f, s1 = 0.0f;
#pragma unroll
            for (int nf = 0; nf < 8; nf++) {
                const int col = hc + wn * 64 + nf * 8 + (lane & 3) * 2;
                const float bb0 = __ldg(b1b + col),     bb1 = __ldg(b1b + col + 1);
                const float ww0 = __ldg(w2b + col),     ww1 = __ldg(w2b + col + 1);
                float v;
                v = fmaxf(acc[mf][nf][0] + bb0, 0.0f); s0 = fmaf(v, ww0, s0);
                v = fmaxf(acc[mf][nf][1] + bb1, 0.0f); s0 = fmaf(v, ww1, s0);
                v = fmaxf(acc[mf][nf][2] + bb0, 0.0f); s1 = fmaf(v, ww0, s1);
                v = fmaxf(acc[mf][nf][3] + bb1, 0.0f); s1 = fmaf(v, ww1, s1);
            }
            s0 += __shfl_xor_sync(0xFFFFFFFFu, s0, 1);
            s0 += __shfl_xor_sync(0xFFFFFFFFu, s0, 2);
            s1 += __shfl_xor_sync(0xFFFFFFFFu, s1, 1);
            s1 += __shfl_xor_sync(0xFFFFFFFFu, s1, 2);
            if ((lane & 3) == 0) {
                const int r0 = wm * 32 + mf * 16 + (lane >> 2);
                atomicAdd(&red[r0], s0);
                atomicAdd(&red[r0 + 8], s1);
            }
        }
    }

    __syncthreads();
    if (tid < M_TILE)
        out[(size_t)(t0 + tid) * B_DIM + b] = red[tid] + bias2;
}

// ---------------- launch ----------------
extern "C" void kernel_launch(void* const* d_in, const int* in_sizes, int n_in,
                              void* d_out, int out_size)
{
    const float* x  = (const float*)d_in[0];   // [T,B,F]
    const float* w1 = (const float*)d_in[1];   // [B,F,H]
    const float* b1 = (const float*)d_in[2];   // [B,H]
    const float* w2 = (const float*)d_in[3];   // [B,H,1]
    const float* b2 = (const float*)d_in[4];   // [B,1]
    float* out = (float*)d_out;                // [T,B,1]

    {
        const size_t total = (size_t)T_DIM * B_DIM * F_DIM;   // 16,777,216
        convert_x_kernel<<<(int)(total / 4 / 256), 256>>>(x);
    }
    {
        const size_t total = (size_t)B_DIM * F_DIM * H_DIM;   // 4,194,304
        convert_w1_kernel<<<(int)(total / 4 / 256), 256>>>(w1);
    }
    {
        cudaFuncSetAttribute(mothernet_mma_kernel,
                             cudaFuncAttributeMaxDynamicSharedMemorySize, SMEM_DYN);
        dim3 g(T_DIM / M_TILE, B_DIM);
        mothernet_mma_kernel<<<g, 256, SMEM_DYN>>>(b1, w2, b2, out);
    }
}